// round 5
// baseline (speedup 1.0000x reference)
#include <cuda_runtime.h>
#include <cuda_fp16.h>
#include <math.h>

#define WARPS_PER_BLOCK 8
#define THREADS_PER_BLOCK (WARPS_PER_BLOCK * 32)
#define FULL_MASK 0xffffffffu
#define MAX_NODES 100000
#define FEAT 64

// fp16 staging of node_value: one row = 64 halves = 128B = ONE 128B line,
// halving L1 wavefronts and L2 bytes for the random gather (the binder).
__device__ __half2 g_value_h[(size_t)MAX_NODES * (FEAT / 2)];

// Index width (int32 vs int64) detected from raw words of row_ptr:
//   int32: [0, D, 2D, ...]  -> raw[1] != 0
//   int64: [0,0, D,0, ...]  -> raw[1] == 0 && raw[2] != 0
__device__ __forceinline__ long long load_index(const void* p, long long i, int is64)
{
    return is64 ? ((const long long*)p)[i] : (long long)((const int*)p)[i];
}

__global__ void __launch_bounds__(256)
convert_to_half_kernel(const float2* __restrict__ node_value2, int n_half2)
{
    const int i = blockIdx.x * blockDim.x + threadIdx.x;
    if (i < n_half2) {
        const float2 f = node_value2[i];
        g_value_h[i] = __floats2half2_rn(f.x, f.y);
    }
}

// One warp per destination node. Softmax over 16 edge scores, then weighted
// gather-accumulate. Each lane owns 2 feature columns (one half2): each
// edge's gather is a single 128B warp transaction = 1 L1 wavefront.
__global__ void __launch_bounds__(THREADS_PER_BLOCK)
gat_aggregate_kernel(const void*   __restrict__ row_ptr_raw,
                     const void*   __restrict__ col_idx_raw,
                     const float*  __restrict__ edge_scores,
                     const float2* __restrict__ node_value2,  // fp32 fallback
                     float2*       __restrict__ out2,         // [N, 32] float2
                     int num_nodes)
{
    const int node = blockIdx.x * WARPS_PER_BLOCK + (threadIdx.x >> 5);
    if (node >= num_nodes) return;
    const int lane = threadIdx.x & 31;

    // uniform per-grid: detect index width (L2-broadcast loads, ~free)
    const unsigned* rp_raw = (const unsigned*)row_ptr_raw;
    const int is64 = (rp_raw[1] == 0u && rp_raw[2] != 0u) ? 1 : 0;

    const long long start = load_index(row_ptr_raw, node, is64);
    const long long end   = load_index(row_ptr_raw, node + 1, is64);
    const int deg = (int)(end - start);

    float2 acc = make_float2(0.0f, 0.0f);

    if (deg == 16) {
        // ---- fast path: degree exactly 16 (this dataset) ----
        float s = -INFINITY;
        unsigned c = 0;
        if (lane < 16) {
            s = edge_scores[start + lane];
            c = (unsigned)load_index(col_idx_raw, start + lane, is64);
        }
        float m = s;
        #pragma unroll
        for (int off = 8; off > 0; off >>= 1)
            m = fmaxf(m, __shfl_xor_sync(FULL_MASK, m, off));

        float w = (lane < 16) ? __expf(s - m) : 0.0f;
        float sum = w;
        #pragma unroll
        for (int off = 8; off > 0; off >>= 1)
            sum += __shfl_xor_sync(FULL_MASK, sum, off);

        w *= __frcp_rn(sum);

        // 16 fully-unrolled fp16 gathers (1 line each); fp32 accumulate.
        #pragma unroll
        for (int e = 0; e < 16; e++) {
            const float    bw = __shfl_sync(FULL_MASK, w, e);
            const unsigned bc = __shfl_sync(FULL_MASK, c, e);
            const float2 v = __half22float2(g_value_h[(size_t)bc * 32 + lane]);
            acc.x = fmaf(bw, v.x, acc.x);
            acc.y = fmaf(bw, v.y, acc.y);
        }
    } else if (deg > 0) {
        // ---- generic path: any degree (not taken on this dataset).
        //      Uses full-precision node_value directly. ----
        float m = -INFINITY;
        for (int e = lane; e < deg; e += 32)
            m = fmaxf(m, edge_scores[start + e]);
        #pragma unroll
        for (int off = 16; off > 0; off >>= 1)
            m = fmaxf(m, __shfl_xor_sync(FULL_MASK, m, off));

        float sum = 0.0f;
        for (int e = lane; e < deg; e += 32)
            sum += __expf(edge_scores[start + e] - m);
        #pragma unroll
        for (int off = 16; off > 0; off >>= 1)
            sum += __shfl_xor_sync(FULL_MASK, sum, off);
        const float inv = __frcp_rn(sum);

        for (int e = 0; e < deg; e++) {
            const float bs = edge_scores[start + e];
            const unsigned bc = (unsigned)load_index(col_idx_raw, start + e, is64);
            const float bw = __expf(bs - m) * inv;
            const float2 v = node_value2[(size_t)bc * 32 + lane];
            acc.x = fmaf(bw, v.x, acc.x);
            acc.y = fmaf(bw, v.y, acc.y);
        }
    }
    // deg == 0 -> zeros

    out2[(size_t)node * 32 + lane] = acc;
}

extern "C" void kernel_launch(void* const* d_in, const int* in_sizes, int n_in,
                              void* d_out, int out_size)
{
    const void*   row_ptr     = d_in[0];
    const void*   col_idx     = d_in[1];
    const float*  edge_scores = (const float*)d_in[2];
    const float2* node_value2 = (const float2*)d_in[3];
    float2*       out2        = (float2*)d_out;

    const int num_nodes = in_sizes[0] - 1;
    const int n_half2   = in_sizes[3] / 2;   // total floats / 2

    convert_to_half_kernel<<<(n_half2 + 255) / 256, 256>>>(node_value2, n_half2);

    const int grid = (num_nodes + WARPS_PER_BLOCK - 1) / WARPS_PER_BLOCK;
    gat_aggregate_kernel<<<grid, THREADS_PER_BLOCK>>>(
        row_ptr, col_idx, edge_scores, node_value2, out2, num_nodes);
}

// round 6
// speedup vs baseline: 1.5178x; 1.5178x over previous
#include <cuda_runtime.h>
#include <math.h>

#define WARPS_PER_BLOCK 8
#define THREADS_PER_BLOCK (WARPS_PER_BLOCK * 32)
#define FULL_MASK 0xffffffffu

// Index width (int32 vs int64) detected from raw words of row_ptr:
//   int32: [0, D, 2D, ...]  -> raw[1] != 0
//   int64: [0,0, D,0, ...]  -> raw[1] == 0 && raw[2] != 0
__device__ __forceinline__ long long load_index(const void* p, long long i, int is64)
{
    return is64 ? ((const long long*)p)[i] : (long long)((const int*)p)[i];
}

// TWO nodes per warp. The 32 edges of node pair (2p, 2p+1) are contiguous in
// CSR, so all 32 lanes load one score+col each. The butterfly reduction with
// offsets 8,4,2,1 computes softmax independently in each 16-lane half (one
// half per node). Gather: lane owns 4 features (float4); half-warp h handles
// node 2p+h's edges, so one LDG.128 instruction serves TWO edges.
__global__ void __launch_bounds__(THREADS_PER_BLOCK)
gat_aggregate_kernel(const void*   __restrict__ row_ptr_raw,
                     const void*   __restrict__ col_idx_raw,
                     const float*  __restrict__ edge_scores,
                     const float4* __restrict__ node_value4,  // [N, 16] float4
                     float4*       __restrict__ out4,         // [N, 16] float4
                     int num_nodes)
{
    const int pair = blockIdx.x * WARPS_PER_BLOCK + (threadIdx.x >> 5);
    const int nodeA = 2 * pair;
    if (nodeA >= num_nodes) return;
    const int lane = threadIdx.x & 31;
    const int half = lane >> 4;
    const int sub  = lane & 15;

    // uniform per-grid: detect index width (L2-broadcast loads, ~free)
    const unsigned* rp_raw = (const unsigned*)row_ptr_raw;
    const int is64 = (rp_raw[1] == 0u && rp_raw[2] != 0u) ? 1 : 0;

    const long long start = load_index(row_ptr_raw, nodeA, is64);
    const bool haveB = (nodeA + 1) < num_nodes;
    const long long mid = haveB ? load_index(row_ptr_raw, nodeA + 1, is64) : start;
    const long long end = haveB ? load_index(row_ptr_raw, nodeA + 2, is64)
                                : mid;

    if (haveB && (mid - start) == 16 && (end - mid) == 16) {
        // ---- fast path: both nodes have degree 16 (this dataset) ----
        const float    s = edge_scores[start + lane];
        const unsigned c = (unsigned)load_index(col_idx_raw, start + lane, is64);

        // per-half softmax (halves never mix with offsets <= 8)
        float m = s;
        #pragma unroll
        for (int off = 8; off > 0; off >>= 1)
            m = fmaxf(m, __shfl_xor_sync(FULL_MASK, m, off));

        float w = __expf(s - m);
        float sum = w;
        #pragma unroll
        for (int off = 8; off > 0; off >>= 1)
            sum += __shfl_xor_sync(FULL_MASK, sum, off);

        w *= __frcp_rn(sum);

        // gather: iteration e serves edge e of BOTH nodes (one LDG.128).
        const int base = half << 4;   // this half reads its own node's edges
        float4 acc = make_float4(0.0f, 0.0f, 0.0f, 0.0f);
        #pragma unroll
        for (int e = 0; e < 16; e++) {
            const float    bw = __shfl_sync(FULL_MASK, w, base + e);
            const unsigned bc = __shfl_sync(FULL_MASK, c, base + e);
            const float4 v = node_value4[(size_t)bc * 16 + sub];
            acc.x = fmaf(bw, v.x, acc.x);
            acc.y = fmaf(bw, v.y, acc.y);
            acc.z = fmaf(bw, v.z, acc.z);
            acc.w = fmaf(bw, v.w, acc.w);
        }

        out4[(size_t)(nodeA + half) * 16 + sub] = acc;
    } else {
        // ---- generic path: any degree (not taken on this dataset) ----
        for (int which = 0; which < 2; which++) {
            const int node = nodeA + which;
            if (node >= num_nodes) break;
            const long long s0 = load_index(row_ptr_raw, node, is64);
            const long long s1 = load_index(row_ptr_raw, node + 1, is64);
            const int deg = (int)(s1 - s0);

            float m = -INFINITY;
            for (int e = lane; e < deg; e += 32)
                m = fmaxf(m, edge_scores[s0 + e]);
            #pragma unroll
            for (int off = 16; off > 0; off >>= 1)
                m = fmaxf(m, __shfl_xor_sync(FULL_MASK, m, off));

            float sum = 0.0f;
            for (int e = lane; e < deg; e += 32)
                sum += __expf(edge_scores[s0 + e] - m);
            #pragma unroll
            for (int off = 16; off > 0; off >>= 1)
                sum += __shfl_xor_sync(FULL_MASK, sum, off);
            const float inv = (deg > 0) ? __frcp_rn(sum) : 0.0f;

            float4 acc = make_float4(0.0f, 0.0f, 0.0f, 0.0f);
            // lane covers feature slot (lane&15); both halves duplicate work
            for (int e = 0; e < deg; e++) {
                const float bs = edge_scores[s0 + e];
                const unsigned bc = (unsigned)load_index(col_idx_raw, s0 + e, is64);
                const float bw = __expf(bs - m) * inv;
                const float4 v = node_value4[(size_t)bc * 16 + sub];
                acc.x = fmaf(bw, v.x, acc.x);
                acc.y = fmaf(bw, v.y, acc.y);
                acc.z = fmaf(bw, v.z, acc.z);
                acc.w = fmaf(bw, v.w, acc.w);
            }
            if (half == 0)
                out4[(size_t)node * 16 + sub] = acc;
        }
    }
}

extern "C" void kernel_launch(void* const* d_in, const int* in_sizes, int n_in,
                              void* d_out, int out_size)
{
    const void*   row_ptr     = d_in[0];
    const void*   col_idx     = d_in[1];
    const float*  edge_scores = (const float*)d_in[2];
    const float4* node_value4 = (const float4*)d_in[3];
    float4*       out4        = (float4*)d_out;

    const int num_nodes = in_sizes[0] - 1;
    const int num_pairs = (num_nodes + 1) / 2;
    const int grid = (num_pairs + WARPS_PER_BLOCK - 1) / WARPS_PER_BLOCK;

    gat_aggregate_kernel<<<grid, THREADS_PER_BLOCK>>>(
        row_ptr, col_idx, edge_scores, node_value4, out4, num_nodes);
}